// round 15
// baseline (speedup 1.0000x reference)
#include <cuda_runtime.h>
#include <cuda_bf16.h>
#include <cstdint>

#define BB 256
#define SS 512
#define DD 1024
#define TT 17
#define EST 20   // padded eem row stride (16B-aligned rows)

// ---------------- device scratch (no allocations allowed) ----------------
__device__ float g_eem[(size_t)BB * SS * EST];  // exp(em - rowmax), 10.5 MB
__device__ float g_part_score[1024];            // per-CTA numerator partials
__device__ float g_part_msum[1024];             // per-CTA sum of masked row-maxes
__device__ int   g_part_mcnt[1024];             // per-CTA mask counts
__device__ float g_denom[BB];                   // log partition minus msum offset

// ---------------- smem layout (bytes) ----------------
#define SM_B    0                       // W bf16: 24 n-rows x 1024 k = 48 KB
#define SM_A    49152                   // 4 warps x 1 buf x 4 KB = 16 KB
#define SM_D    SM_A                    // D reuse: 128 x 26 fp32 = 13312 B
#define SM_RED  (SM_A + 16384)          // 65536
#define SM_TOT  (SM_RED + 64)           // 65600

__device__ __forceinline__ uint2 cvt_f4_bf16x4(float4 f) {
    uint2 r;
    // low 16 bits = earlier k element
    asm("cvt.rn.bf16x2.f32 %0, %1, %2;" : "=r"(r.x) : "f"(f.y), "f"(f.x));
    asm("cvt.rn.bf16x2.f32 %0, %1, %2;" : "=r"(r.y) : "f"(f.w), "f"(f.z));
    return r;
}

__device__ __forceinline__ void mma16816(float* d, const uint32_t* a,
                                         const uint32_t* b) {
    asm volatile(
        "mma.sync.aligned.m16n8k16.row.col.f32.bf16.bf16.f32 "
        "{%0,%1,%2,%3}, {%4,%5,%6,%7}, {%8,%9}, {%0,%1,%2,%3};"
        : "+f"(d[0]), "+f"(d[1]), "+f"(d[2]), "+f"(d[3])
        : "r"(a[0]), "r"(a[1]), "r"(a[2]), "r"(a[3]), "r"(b[0]), "r"(b[1]));
}

// ============================================================
// Kernel 1: HMMA emissions GEMM + eem/rowmax + numerator partials
//   1024 CTAs x 128 threads, 2 CTAs/SM; 2-deep raw prefetch
//   (32 LDG.128 in flight per warp) for DRAM latency cover.
// ============================================================
__global__ void __launch_bounds__(128, 2)
emis_kernel(const float* __restrict__ data, const int* __restrict__ labels,
            const int* __restrict__ mask, const float* __restrict__ W,
            const float* __restrict__ bias, const float* __restrict__ start,
            const float* __restrict__ trans)
{
    extern __shared__ char smem[];
    const int tid = threadIdx.x;
    const int blk = blockIdx.x;
    const int w   = tid >> 5;
    const int l   = tid & 31;

    // ---- stage B = W as bf16 [24 n x 1024 k], swizzled ----
    for (int i = tid; i < 896; i += 128)
        reinterpret_cast<uint4*>(smem + SM_B + 17 * 2048)[i] =
            make_uint4(0u, 0u, 0u, 0u);
    const float4* W4 = reinterpret_cast<const float4*>(W);
    for (int i = tid; i < TT * DD / 4; i += 128) {
        int n = i >> 8, k4 = i & 255;
        uint32_t off = (uint32_t)(n * 2048 + ((k4 * 8) ^ ((n & 7) << 4)));
        *reinterpret_cast<uint2*>(smem + SM_B + off) =
            cvt_f4_bf16x4(__ldg(W4 + i));
    }

    // ---- A staging geometry (warp-private, single 4 KB buffer) ----
    const int lr8 = l >> 4;
    const int q   = l & 15;
    const float4* dq = reinterpret_cast<const float4*>(data);
    const long g0 = (long)(blk * 128 + w * 32 + lr8) * 256 + q;
    char* buf = smem + SM_A + w * 4096;

    // 2-deep raw prefetch: chunks 0 and 1 in flight before the loop
    float4 rawA[16], rawB[16];
    #pragma unroll
    for (int i = 0; i < 16; i++)
        rawA[i] = __ldg(dq + g0 + (long)i * 512);
    #pragma unroll
    for (int i = 0; i < 16; i++)
        rawB[i] = __ldg(dq + g0 + (long)i * 512 + 16);

    __syncthreads();   // B ready

    float acc[2][3][4];
    #pragma unroll
    for (int mt = 0; mt < 2; mt++)
        #pragma unroll
        for (int nt = 0; nt < 3; nt++)
            #pragma unroll
            for (int x = 0; x < 4; x++) acc[mt][nt][x] = 0.0f;

    const int rk = l >> 2;
    const int cx = (l & 3) * 4;
    const uint32_t keysh = (uint32_t)rk << 4;
    char* sB = smem + SM_B;

    #define STS_CHUNK(RAW)                                                      \
        do {                                                                     \
            _Pragma("unroll")                                                    \
            for (int i = 0; i < 16; i++) {                                       \
                uint2 pk = cvt_f4_bf16x4(RAW[i]);                                \
                *reinterpret_cast<uint2*>(                                       \
                    buf + (i * 2 + lr8) * 128 +                                  \
                    ((q * 8) ^ (((i & 3) * 2 + lr8) << 4))) = pk;                \
            }                                                                    \
        } while (0)

    #define LDG_CHUNK(RAW, CC)                                                  \
        do {                                                                     \
            _Pragma("unroll")                                                    \
            for (int i = 0; i < 16; i++)                                         \
                RAW[i] = __ldg(dq + g0 + (long)i * 512 + (CC) * 16);             \
        } while (0)

    #define MMA_CHUNK(CC)                                                       \
        do {                                                                     \
            _Pragma("unroll")                                                    \
            for (int ks = 0; ks < 4; ks++) {                                     \
                const uint32_t a0o = (uint32_t)(rk * 128) +                      \
                    (((uint32_t)(ks * 32 + cx)) ^ keysh);                        \
                uint32_t aA[2][4];                                               \
                _Pragma("unroll")                                                \
                for (int mt = 0; mt < 2; mt++) {                                 \
                    char* bm = buf + mt * 2048;                                  \
                    aA[mt][0] = *reinterpret_cast<uint32_t*>(bm + a0o);          \
                    aA[mt][1] = *reinterpret_cast<uint32_t*>(bm + a0o + 1024);   \
                    aA[mt][2] = *reinterpret_cast<uint32_t*>(bm + (a0o ^ 16));   \
                    aA[mt][3] = *reinterpret_cast<uint32_t*>(bm + (a0o ^ 16) + 1024); \
                }                                                                \
                _Pragma("unroll")                                                \
                for (int nt = 0; nt < 3; nt++) {                                 \
                    const uint32_t b0o = (uint32_t)((nt * 8 + rk) * 2048) +      \
                        (((uint32_t)((CC) * 128 + ks * 32 + cx)) ^ keysh);       \
                    uint32_t bb[2];                                              \
                    bb[0] = *reinterpret_cast<uint32_t*>(sB + b0o);              \
                    bb[1] = *reinterpret_cast<uint32_t*>(sB + (b0o ^ 16));       \
                    mma16816(acc[0][nt], aA[0], bb);                             \
                    mma16816(acc[1][nt], aA[1], bb);                             \
                }                                                                \
            }                                                                    \
        } while (0)

    #pragma unroll 1
    for (int c = 0; c < 16; c += 2) {
        STS_CHUNK(rawA);
        __syncwarp();
        if (c + 2 < 16) LDG_CHUNK(rawA, c + 2);
        MMA_CHUNK(c);
        __syncwarp();

        STS_CHUNK(rawB);
        __syncwarp();
        if (c + 3 < 16) LDG_CHUNK(rawB, c + 3);
        MMA_CHUNK(c + 1);
        __syncwarp();
    }
    #undef STS_CHUNK
    #undef LDG_CHUNK
    #undef MMA_CHUNK

    // ---- D -> smem (stride 26 floats), then per-thread row epilogue ----
    __syncthreads();
    float* sD = reinterpret_cast<float*>(smem + SM_D);
    #pragma unroll
    for (int mt = 0; mt < 2; mt++)
        #pragma unroll
        for (int nt = 0; nt < 3; nt++) {
            int r  = w * 32 + mt * 16 + rk;
            int cb = nt * 8 + (l & 3) * 2;
            *reinterpret_cast<float2*>(sD + r * 26 + cb) =
                make_float2(acc[mt][nt][0], acc[mt][nt][1]);
            *reinterpret_cast<float2*>(sD + (r + 8) * 26 + cb) =
                make_float2(acc[mt][nt][2], acc[mt][nt][3]);
        }
    __syncthreads();

    const int row = blk * 128 + tid;
    const int s   = row & (SS - 1);

    float emv[TT];
    float m = -1e30f;
    #pragma unroll
    for (int t = 0; t < TT; t++) {
        emv[t] = sD[tid * 26 + t] + __ldg(bias + t);
        m = fmaxf(m, emv[t]);
    }
    float e[TT];
    #pragma unroll
    for (int t = 0; t < TT; t++) e[t] = __expf(emv[t] - m);

    float4* o4 = reinterpret_cast<float4*>(g_eem + (size_t)row * EST);
    o4[0] = make_float4(e[0],  e[1],  e[2],  e[3]);
    o4[1] = make_float4(e[4],  e[5],  e[6],  e[7]);
    o4[2] = make_float4(e[8],  e[9],  e[10], e[11]);
    o4[3] = make_float4(e[12], e[13], e[14], e[15]);
    o4[4] = make_float4(e[16], 0.0f,  0.0f,  0.0f);

    int lab = __ldg(labels + row);
    float em_lab = 0.0f;
    #pragma unroll
    for (int t = 0; t < TT; t++) em_lab = (lab == t) ? emv[t] : em_lab;

    float mk = (__ldg(mask + row) != 0) ? 1.0f : 0.0f;
    float contrib;
    if (s == 0) {
        contrib = __ldg(start + lab) + em_lab;
    } else {
        int prev = __ldg(labels + row - 1);
        contrib = mk * (__ldg(trans + prev * TT + lab) + em_lab);
    }
    float msum_t = mk * m;
    int   mcnt_t = (mk > 0.0f) ? 1 : 0;

    const unsigned FULL = 0xffffffffu;
    #pragma unroll
    for (int off = 16; off; off >>= 1) {
        contrib += __shfl_xor_sync(FULL, contrib, off);
        msum_t  += __shfl_xor_sync(FULL, msum_t, off);
        mcnt_t  += __shfl_xor_sync(FULL, mcnt_t, off);
    }
    float* red = reinterpret_cast<float*>(smem + SM_RED);
    if (l == 0) {
        red[w]     = contrib;
        red[4 + w] = msum_t;
        reinterpret_cast<int*>(red)[8 + w] = mcnt_t;
    }
    __syncthreads();
    if (tid == 0) {
        float sc = 0.0f, sm = 0.0f; int cn = 0;
        #pragma unroll
        for (int ww = 0; ww < 4; ww++) {
            sc += red[ww];
            sm += red[4 + ww];
            cn += reinterpret_cast<int*>(red)[8 + ww];
        }
        g_part_score[blk] = sc;
        g_part_msum[blk]  = sm;
        g_part_mcnt[blk]  = cn;
    }
}

// ============================================================
// Kernel 2: CRF forward recurrence (linear domain)
//   Lean BRANCHLESS step (FSEL), renorm once per 8-step chunk.
//   128 blocks x 64 threads, 1 warp per batch.
// ============================================================
__global__ void __launch_bounds__(64)
crf_kernel(const float* __restrict__ trans, const float* __restrict__ start,
           const float* __restrict__ endt, const int* __restrict__ mask)
{
    const unsigned FULL = 0xffffffffu;
    int b = blockIdx.x * 2 + (threadIdx.x >> 5);
    int j = threadIdx.x & 31;
    bool act = (j < TT);

    float Ecol[TT];
    #pragma unroll
    for (int i = 0; i < TT; i++)
        Ecol[i] = act ? __expf(__ldg(trans + i * TT + j)) : 0.0f;
    float eend = act ? __expf(__ldg(endt + j)) : 0.0f;

    const float* eb = g_eem + (size_t)b * (SS * EST);
    const int4* mb = reinterpret_cast<const int4*>(mask + b * SS);

    float bufA[8], bufB[8];
    int   mA[8],  mB[8];

    #pragma unroll
    for (int d = 0; d < 8; d++)
        bufA[d] = act ? __ldg(eb + d * EST + j) : 0.0f;
    {
        int4 a = __ldg(mb + 0), c = __ldg(mb + 1);
        mA[0]=a.x; mA[1]=a.y; mA[2]=a.z; mA[3]=a.w;
        mA[4]=c.x; mA[5]=c.y; mA[6]=c.z; mA[7]=c.w;
    }

    float p = act ? bufA[0] * __expf(__ldg(start + j)) : 0.0f;
    float C = 0.0f;

    // branchless lean step: masked -> p unchanged (FSEL only)
    auto step = [&](float eemv, int mkv) {
        float a[4] = {0.f, 0.f, 0.f, 0.f};
        #pragma unroll
        for (int i = 0; i < TT; i++)
            a[i & 3] = fmaf(__shfl_sync(FULL, p, i), Ecol[i], a[i & 3]);
        float qn = ((a[0] + a[1]) + (a[2] + a[3])) * eemv;
        p = (mkv != 0) ? qn : p;
    };

    // once-per-chunk renorm: p /= p0, C += log p0 (invariant-preserving)
    auto renorm = [&]() {
        float r = __shfl_sync(FULL, p, 0);
        p *= __fdividef(1.0f, r);
        C += __logf(r);
    };

    #define PREFETCH(cidx, BUF, MARR)                                          \
        do {                                                                    \
            _Pragma("unroll")                                                   \
            for (int d = 0; d < 8; d++)                                         \
                BUF[d] = act ? __ldg(eb + ((cidx) * 8 + d) * EST + j) : 0.0f;   \
            int4 _a = __ldg(mb + 2 * (cidx)), _c = __ldg(mb + 2 * (cidx) + 1);  \
            MARR[0]=_a.x; MARR[1]=_a.y; MARR[2]=_a.z; MARR[3]=_a.w;             \
            MARR[4]=_c.x; MARR[5]=_c.y; MARR[6]=_c.z; MARR[7]=_c.w;             \
        } while (0)

    #define PROCESS(BUF, MARR)                                                  \
        do {                                                                    \
            _Pragma("unroll")                                                   \
            for (int d = 0; d < 8; d++) step(BUF[d], MARR[d]);                  \
            renorm();                                                           \
        } while (0)

    PREFETCH(1, bufB, mB);
    #pragma unroll
    for (int d = 1; d < 8; d++) step(bufA[d], mA[d]);
    renorm();

    for (int cc = 1; cc < 63; cc += 2) {
        PREFETCH(cc + 1, bufA, mA);
        PROCESS(bufB, mB);
        PREFETCH(cc + 2, bufB, mB);
        PROCESS(bufA, mA);
    }
    PROCESS(bufB, mB);

    float term = p * eend;
    #pragma unroll
    for (int off = 16; off; off >>= 1)
        term += __shfl_xor_sync(FULL, term, off);
    if (j == 0) g_denom[b] = C + __logf(term);

    #undef PREFETCH
    #undef PROCESS
}

// ============================================================
// Kernel 3: finalize  out = -mean(score - denom)
// ============================================================
__global__ void __launch_bounds__(256)
fin_kernel(const int* __restrict__ labels, const float* __restrict__ endt,
           float* __restrict__ out)
{
    __shared__ float sred[256];
    int b = threadIdx.x;
    int cnt = 0;
    float psc = 0.0f, pms = 0.0f;
    #pragma unroll
    for (int k = 0; k < 4; k++) {
        cnt += g_part_mcnt[4 * b + k];
        psc += g_part_score[4 * b + k];
        pms += g_part_msum[4 * b + k];
    }
    int lt = __ldg(labels + b * SS + (cnt - 1));
    float score = psc + __ldg(endt + lt);
    float denom = g_denom[b] + pms;
    sred[b] = score - denom;
    __syncthreads();
    #pragma unroll
    for (int off = 128; off; off >>= 1) {
        if (b < off) sred[b] += sred[b + off];
        __syncthreads();
    }
    if (b == 0) out[0] = -sred[0] * (1.0f / BB);
}

// ============================================================
extern "C" void kernel_launch(void* const* d_in, const int* in_sizes, int n_in,
                              void* d_out, int out_size)
{
    const float* data   = (const float*)d_in[0];
    const int*   labels = (const int*)d_in[1];
    const int*   mask   = (const int*)d_in[2];
    const float* W      = (const float*)d_in[3];
    const float* bias   = (const float*)d_in[4];
    const float* start  = (const float*)d_in[5];
    const float* endt   = (const float*)d_in[6];
    const float* trans  = (const float*)d_in[7];

    cudaFuncSetAttribute(emis_kernel,
                         cudaFuncAttributeMaxDynamicSharedMemorySize, SM_TOT);

    emis_kernel<<<1024, 128, SM_TOT>>>(data, labels, mask, W, bias, start, trans);
    crf_kernel<<<BB / 2, 64>>>(trans, start, endt, mask);
    fin_kernel<<<1, 256>>>(labels, endt, (float*)d_out);
}

// round 16
// speedup vs baseline: 1.0972x; 1.0972x over previous
#include <cuda_runtime.h>
#include <cuda_bf16.h>
#include <cstdint>

#define BB 256
#define SS 512
#define DD 1024
#define TT 17
#define EST 20   // padded eem row stride (16B-aligned rows)
#define GRID_P 444   // 148 SMs x 3 CTAs

// ---------------- device scratch (no allocations allowed) ----------------
__device__ float g_eem[(size_t)BB * SS * EST];  // exp(em - rowmax), 10.5 MB
__device__ float g_part_score[1024];            // per-tile numerator partials
__device__ float g_part_msum[1024];             // per-tile sum of masked row-maxes
__device__ int   g_part_mcnt[1024];             // per-tile mask counts
__device__ float g_denom[BB];                   // log partition minus msum offset

// ---------------- smem layout (bytes) ----------------
#define SM_B    0                       // W bf16: 24 n-rows x 1024 k = 48 KB
#define SM_A    49152                   // 4 warps x 1 buf x 4 KB = 16 KB
#define SM_D    SM_A                    // D reuse: 128 x 26 fp32 = 13312 B
#define SM_RED  (SM_A + 16384)          // 65536
#define SM_TOT  (SM_RED + 64)           // 65600

__device__ __forceinline__ uint2 cvt_f4_bf16x4(float4 f) {
    uint2 r;
    // low 16 bits = earlier k element
    asm("cvt.rn.bf16x2.f32 %0, %1, %2;" : "=r"(r.x) : "f"(f.y), "f"(f.x));
    asm("cvt.rn.bf16x2.f32 %0, %1, %2;" : "=r"(r.y) : "f"(f.w), "f"(f.z));
    return r;
}

__device__ __forceinline__ void mma16816(float* d, const uint32_t* a,
                                         const uint32_t* b) {
    asm volatile(
        "mma.sync.aligned.m16n8k16.row.col.f32.bf16.bf16.f32 "
        "{%0,%1,%2,%3}, {%4,%5,%6,%7}, {%8,%9}, {%0,%1,%2,%3};"
        : "+f"(d[0]), "+f"(d[1]), "+f"(d[2]), "+f"(d[3])
        : "r"(a[0]), "r"(a[1]), "r"(a[2]), "r"(a[3]), "r"(b[0]), "r"(b[1]));
}

// ============================================================
// Kernel 1: HMMA emissions GEMM + eem/rowmax + numerator partials
//   PERSISTENT: 444 CTAs x 128 threads, 3/SM; each CTA loops tiles
//   (B staged once per CTA; no wave transitions).
// ============================================================
__global__ void __launch_bounds__(128, 3)
emis_kernel(const float* __restrict__ data, const int* __restrict__ labels,
            const int* __restrict__ mask, const float* __restrict__ W,
            const float* __restrict__ bias, const float* __restrict__ start,
            const float* __restrict__ trans)
{
    extern __shared__ char smem[];
    const int tid = threadIdx.x;
    const int w   = tid >> 5;
    const int l   = tid & 31;

    // ---- stage B = W as bf16 [24 n x 1024 k], swizzled (once) ----
    for (int i = tid; i < 896; i += 128)
        reinterpret_cast<uint4*>(smem + SM_B + 17 * 2048)[i] =
            make_uint4(0u, 0u, 0u, 0u);
    const float4* W4 = reinterpret_cast<const float4*>(W);
    for (int i = tid; i < TT * DD / 4; i += 128) {
        int n = i >> 8, k4 = i & 255;
        uint32_t off = (uint32_t)(n * 2048 + ((k4 * 8) ^ ((n & 7) << 4)));
        *reinterpret_cast<uint2*>(smem + SM_B + off) =
            cvt_f4_bf16x4(__ldg(W4 + i));
    }
    __syncthreads();   // B ready

    const int lr8 = l >> 4;
    const int q   = l & 15;
    const float4* dq = reinterpret_cast<const float4*>(data);
    char* buf = smem + SM_A + w * 4096;
    const int rk = l >> 2;
    const int cx = (l & 3) * 4;
    const uint32_t keysh = (uint32_t)rk << 4;
    char* sB = smem + SM_B;
    float* sD = reinterpret_cast<float*>(smem + SM_D);
    float* red = reinterpret_cast<float*>(smem + SM_RED);
    const unsigned FULL = 0xffffffffu;

    for (int tile = blockIdx.x; tile < 1024; tile += GRID_P) {
        const long g0 = (long)(tile * 128 + w * 32 + lr8) * 256 + q;

        // prefetch chunk 0 RAW (16 clean LDG.128 in flight)
        float4 raw[16];
        #pragma unroll
        for (int i = 0; i < 16; i++)
            raw[i] = __ldg(dq + g0 + (long)i * 512);

        float acc[2][3][4];
        #pragma unroll
        for (int mt = 0; mt < 2; mt++)
            #pragma unroll
            for (int nt = 0; nt < 3; nt++)
                #pragma unroll
                for (int x = 0; x < 4; x++) acc[mt][nt][x] = 0.0f;

        #pragma unroll 1
        for (int c = 0; c < 16; c++) {
            // CVT + STS of current chunk
            #pragma unroll
            for (int i = 0; i < 16; i++) {
                uint2 pk = cvt_f4_bf16x4(raw[i]);
                *reinterpret_cast<uint2*>(
                    buf + (i * 2 + lr8) * 128 +
                    ((q * 8) ^ (((i & 3) * 2 + lr8) << 4))) = pk;
            }
            __syncwarp();

            // prefetch next chunk RAW
            if (c < 15) {
                #pragma unroll
                for (int i = 0; i < 16; i++)
                    raw[i] = __ldg(dq + g0 + (long)i * 512 + (c + 1) * 16);
            }

            // 4 ksteps of k=16
            #pragma unroll
            for (int ks = 0; ks < 4; ks++) {
                const uint32_t a0o = (uint32_t)(rk * 128) +
                    (((uint32_t)(ks * 32 + cx)) ^ keysh);
                uint32_t aA[2][4];
                #pragma unroll
                for (int mt = 0; mt < 2; mt++) {
                    char* bm = buf + mt * 2048;
                    aA[mt][0] = *reinterpret_cast<uint32_t*>(bm + a0o);
                    aA[mt][1] = *reinterpret_cast<uint32_t*>(bm + a0o + 1024);
                    aA[mt][2] = *reinterpret_cast<uint32_t*>(bm + (a0o ^ 16));
                    aA[mt][3] = *reinterpret_cast<uint32_t*>(bm + (a0o ^ 16) + 1024);
                }
                #pragma unroll
                for (int nt = 0; nt < 3; nt++) {
                    const uint32_t b0o = (uint32_t)((nt * 8 + rk) * 2048) +
                        (((uint32_t)(c * 128 + ks * 32 + cx)) ^ keysh);
                    uint32_t bb[2];
                    bb[0] = *reinterpret_cast<uint32_t*>(sB + b0o);
                    bb[1] = *reinterpret_cast<uint32_t*>(sB + (b0o ^ 16));
                    mma16816(acc[0][nt], aA[0], bb);
                    mma16816(acc[1][nt], aA[1], bb);
                }
            }
            __syncwarp();
        }

        // ---- D -> smem (stride 26 floats), per-thread row epilogue ----
        __syncthreads();   // all warps done with A region
        #pragma unroll
        for (int mt = 0; mt < 2; mt++)
            #pragma unroll
            for (int nt = 0; nt < 3; nt++) {
                int r  = w * 32 + mt * 16 + rk;
                int cb = nt * 8 + (l & 3) * 2;
                *reinterpret_cast<float2*>(sD + r * 26 + cb) =
                    make_float2(acc[mt][nt][0], acc[mt][nt][1]);
                *reinterpret_cast<float2*>(sD + (r + 8) * 26 + cb) =
                    make_float2(acc[mt][nt][2], acc[mt][nt][3]);
            }
        __syncthreads();

        const int row = tile * 128 + tid;
        const int s   = row & (SS - 1);

        float emv[TT];
        float m = -1e30f;
        #pragma unroll
        for (int t = 0; t < TT; t++) {
            emv[t] = sD[tid * 26 + t] + __ldg(bias + t);
            m = fmaxf(m, emv[t]);
        }
        float e[TT];
        #pragma unroll
        for (int t = 0; t < TT; t++) e[t] = __expf(emv[t] - m);

        float4* o4 = reinterpret_cast<float4*>(g_eem + (size_t)row * EST);
        o4[0] = make_float4(e[0],  e[1],  e[2],  e[3]);
        o4[1] = make_float4(e[4],  e[5],  e[6],  e[7]);
        o4[2] = make_float4(e[8],  e[9],  e[10], e[11]);
        o4[3] = make_float4(e[12], e[13], e[14], e[15]);
        o4[4] = make_float4(e[16], 0.0f,  0.0f,  0.0f);

        int lab = __ldg(labels + row);
        float em_lab = 0.0f;
        #pragma unroll
        for (int t = 0; t < TT; t++) em_lab = (lab == t) ? emv[t] : em_lab;

        float mk = (__ldg(mask + row) != 0) ? 1.0f : 0.0f;
        float contrib;
        if (s == 0) {
            contrib = __ldg(start + lab) + em_lab;
        } else {
            int prev = __ldg(labels + row - 1);
            contrib = mk * (__ldg(trans + prev * TT + lab) + em_lab);
        }
        float msum_t = mk * m;
        int   mcnt_t = (mk > 0.0f) ? 1 : 0;

        #pragma unroll
        for (int off = 16; off; off >>= 1) {
            contrib += __shfl_xor_sync(FULL, contrib, off);
            msum_t  += __shfl_xor_sync(FULL, msum_t, off);
            mcnt_t  += __shfl_xor_sync(FULL, mcnt_t, off);
        }
        if (l == 0) {
            red[w]     = contrib;
            red[4 + w] = msum_t;
            reinterpret_cast<int*>(red)[8 + w] = mcnt_t;
        }
        __syncthreads();
        if (tid == 0) {
            float sc = 0.0f, sm = 0.0f; int cn = 0;
            #pragma unroll
            for (int ww = 0; ww < 4; ww++) {
                sc += red[ww];
                sm += red[4 + ww];
                cn += reinterpret_cast<int*>(red)[8 + ww];
            }
            g_part_score[tile] = sc;
            g_part_msum[tile]  = sm;
            g_part_mcnt[tile]  = cn;
        }
        __syncthreads();   // red + sD reads done before next tile's STS
    }
}

// ============================================================
// Kernel 2: CRF forward recurrence (linear domain)
//   Split matvec: 9 shfl.idx broadcasts (per-lane src) + 2 xor
//   combines; output 16 computed redundantly by every lane pair.
//   Renorm once per 8-step chunk. 128 blocks x 64 threads.
// ============================================================
__global__ void __launch_bounds__(64)
crf_kernel(const float* __restrict__ trans, const float* __restrict__ start,
           const float* __restrict__ endt, const int* __restrict__ mask)
{
    const unsigned FULL = 0xffffffffu;
    int b = blockIdx.x * 2 + (threadIdx.x >> 5);
    int l = threadIdx.x & 31;
    bool act = (l < TT);
    bool lo  = (l < 16);
    int  j   = l & 15;                 // output column for this lane's pair
    const int base = lo ? 0 : 8;       // i-range start for this lane

    // Em[t] = exp(trans[i][j]) for i = base + t (lo: i=0..7, t=8 zero; hi: i=8..16)
    // E16[t] = exp(trans[i][16]) same i-range (redundant output 16)
    float Em[9], E16[9];
    #pragma unroll
    for (int t = 0; t < 9; t++) {
        int  i = base + t;
        bool v = lo ? (t < 8) : true;
        Em[t]  = v ? __expf(__ldg(trans + i * TT + j))  : 0.0f;
        E16[t] = v ? __expf(__ldg(trans + i * TT + 16)) : 0.0f;
    }
    float eend = act ? __expf(__ldg(endt + l)) : 0.0f;

    const float* eb = g_eem + (size_t)b * (SS * EST);
    const int4* mb = reinterpret_cast<const int4*>(mask + b * SS);

    float bufA[8], bufB[8];
    int   mA[8],  mB[8];

    #pragma unroll
    for (int d = 0; d < 8; d++)
        bufA[d] = act ? __ldg(eb + d * EST + l) : 0.0f;
    {
        int4 a = __ldg(mb + 0), c = __ldg(mb + 1);
        mA[0]=a.x; mA[1]=a.y; mA[2]=a.z; mA[3]=a.w;
        mA[4]=c.x; mA[5]=c.y; mA[6]=c.z; mA[7]=c.w;
    }

    float p = act ? bufA[0] * __expf(__ldg(start + l)) : 0.0f;
    float C = 0.0f;

    // lean step: split matvec, 11 shfls total
    auto step = [&](float eemv, int mkv) {
        if (mkv != 0) {  // warp-uniform
            float qp = 0.0f, q16p = 0.0f;
            #pragma unroll
            for (int t = 0; t < 9; t++) {
                float v = __shfl_sync(FULL, p, base + t);
                qp   = fmaf(v, Em[t],  qp);
                q16p = fmaf(v, E16[t], q16p);
            }
            float qo  = qp   + __shfl_xor_sync(FULL, qp, 16);
            float q16 = q16p + __shfl_xor_sync(FULL, q16p, 16);
            float pn = (l == 16) ? q16 : qo;
            p = act ? pn * eemv : 0.0f;
        }
    };

    // once-per-chunk renorm: p /= p0, C += log p0
    auto renorm = [&]() {
        float r = __shfl_sync(FULL, p, 0);
        p *= __fdividef(1.0f, r);
        C += __logf(r);
    };

    #define PREFETCH(cidx, BUF, MARR)                                          \
        do {                                                                    \
            _Pragma("unroll")                                                   \
            for (int d = 0; d < 8; d++)                                         \
                BUF[d] = act ? __ldg(eb + ((cidx) * 8 + d) * EST + l) : 0.0f;   \
            int4 _a = __ldg(mb + 2 * (cidx)), _c = __ldg(mb + 2 * (cidx) + 1);  \
            MARR[0]=_a.x; MARR[1]=_a.y; MARR[2]=_a.z; MARR[3]=_a.w;             \
            MARR[4]=_c.x; MARR[5]=_c.y; MARR[6]=_c.z; MARR[7]=_c.w;             \
        } while (0)

    #define PROCESS(BUF, MARR)                                                  \
        do {                                                                    \
            _Pragma("unroll")                                                   \
            for (int d = 0; d < 8; d++) step(BUF[d], MARR[d]);                  \
            renorm();                                                           \
        } while (0)

    PREFETCH(1, bufB, mB);
    #pragma unroll
    for (int d = 1; d < 8; d++) step(bufA[d], mA[d]);
    renorm();

    for (int cc = 1; cc < 63; cc += 2) {
        PREFETCH(cc + 1, bufA, mA);
        PROCESS(bufB, mB);
        PREFETCH(cc + 2, bufB, mB);
        PROCESS(bufA, mA);
    }
    PROCESS(bufB, mB);

    float term = p * eend;   // lanes >= 17 contribute 0
    #pragma unroll
    for (int off = 16; off; off >>= 1)
        term += __shfl_xor_sync(FULL, term, off);
    if (l == 0) g_denom[b] = C + __logf(term);

    #undef PREFETCH
    #undef PROCESS
}

// ============================================================
// Kernel 3: finalize  out = -mean(score - denom)
// ============================================================
__global__ void __launch_bounds__(256)
fin_kernel(const int* __restrict__ labels, const float* __restrict__ endt,
           float* __restrict__ out)
{
    __shared__ float sred[256];
    int b = threadIdx.x;
    int cnt = 0;
    float psc = 0.0f, pms = 0.0f;
    #pragma unroll
    for (int k = 0; k < 4; k++) {
        cnt += g_part_mcnt[4 * b + k];
        psc += g_part_score[4 * b + k];
        pms += g_part_msum[4 * b + k];
    }
    int lt = __ldg(labels + b * SS + (cnt - 1));
    float score = psc + __ldg(endt + lt);
    float denom = g_denom[b] + pms;
    sred[b] = score - denom;
    __syncthreads();
    #pragma unroll
    for (int off = 128; off; off >>= 1) {
        if (b < off) sred[b] += sred[b + off];
        __syncthreads();
    }
    if (b == 0) out[0] = -sred[0] * (1.0f / BB);
}

// ============================================================
extern "C" void kernel_launch(void* const* d_in, const int* in_sizes, int n_in,
                              void* d_out, int out_size)
{
    const float* data   = (const float*)d_in[0];
    const int*   labels = (const int*)d_in[1];
    const int*   mask   = (const int*)d_in[2];
    const float* W      = (const float*)d_in[3];
    const float* bias   = (const float*)d_in[4];
    const float* start  = (const float*)d_in[5];
    const float* endt   = (const float*)d_in[6];
    const float* trans  = (const float*)d_in[7];

    cudaFuncSetAttribute(emis_kernel,
                         cudaFuncAttributeMaxDynamicSharedMemorySize, SM_TOT);

    emis_kernel<<<GRID_P, 128, SM_TOT>>>(data, labels, mask, W, bias, start, trans);
    crf_kernel<<<BB / 2, 64>>>(trans, start, endt, mask);
    fin_kernel<<<1, 256>>>(labels, endt, (float*)d_out);
}

// round 17
// speedup vs baseline: 1.1525x; 1.0504x over previous
#include <cuda_runtime.h>
#include <cuda_bf16.h>
#include <cstdint>

#define BB 256
#define SS 512
#define DD 1024
#define TT 17
#define EST 20   // padded eem row stride (16B-aligned rows)
#define GRID_P 444   // 148 SMs x 3 CTAs

// ---------------- device scratch (no allocations allowed) ----------------
__device__ float g_eem[(size_t)BB * SS * EST];  // exp(em - rowmax), 10.5 MB
__device__ float g_part_score[1024];            // per-tile numerator partials
__device__ float g_part_msum[1024];             // per-tile sum of masked row-maxes
__device__ int   g_part_mcnt[1024];             // per-tile mask counts
__device__ float g_denom[BB];                   // log partition minus msum offset

// ---------------- smem layout (bytes) ----------------
#define SM_B    0                       // W bf16: 24 n-rows x 1024 k = 48 KB
#define SM_A    49152                   // 4 warps x 1 buf x 4 KB = 16 KB
#define SM_D    SM_A                    // D reuse: 128 x 26 fp32 = 13312 B
#define SM_RED  (SM_A + 16384)          // 65536
#define SM_TOT  (SM_RED + 64)           // 65600

__device__ __forceinline__ uint2 cvt_f4_bf16x4(float4 f) {
    uint2 r;
    // low 16 bits = earlier k element
    asm("cvt.rn.bf16x2.f32 %0, %1, %2;" : "=r"(r.x) : "f"(f.y), "f"(f.x));
    asm("cvt.rn.bf16x2.f32 %0, %1, %2;" : "=r"(r.y) : "f"(f.w), "f"(f.z));
    return r;
}

__device__ __forceinline__ void mma16816(float* d, const uint32_t* a,
                                         const uint32_t* b) {
    asm volatile(
        "mma.sync.aligned.m16n8k16.row.col.f32.bf16.bf16.f32 "
        "{%0,%1,%2,%3}, {%4,%5,%6,%7}, {%8,%9}, {%0,%1,%2,%3};"
        : "+f"(d[0]), "+f"(d[1]), "+f"(d[2]), "+f"(d[3])
        : "r"(a[0]), "r"(a[1]), "r"(a[2]), "r"(a[3]), "r"(b[0]), "r"(b[1]));
}

// ============================================================
// Kernel 1: HMMA emissions GEMM + eem/rowmax + numerator partials
//   PERSISTENT: 444 CTAs x 128 threads, 3/SM; each CTA loops tiles
//   (B staged once per CTA; no wave transitions). R16 measured-best.
// ============================================================
__global__ void __launch_bounds__(128, 3)
emis_kernel(const float* __restrict__ data, const int* __restrict__ labels,
            const int* __restrict__ mask, const float* __restrict__ W,
            const float* __restrict__ bias, const float* __restrict__ start,
            const float* __restrict__ trans)
{
    extern __shared__ char smem[];
    const int tid = threadIdx.x;
    const int w   = tid >> 5;
    const int l   = tid & 31;

    // ---- stage B = W as bf16 [24 n x 1024 k], swizzled (once) ----
    for (int i = tid; i < 896; i += 128)
        reinterpret_cast<uint4*>(smem + SM_B + 17 * 2048)[i] =
            make_uint4(0u, 0u, 0u, 0u);
    const float4* W4 = reinterpret_cast<const float4*>(W);
    for (int i = tid; i < TT * DD / 4; i += 128) {
        int n = i >> 8, k4 = i & 255;
        uint32_t off = (uint32_t)(n * 2048 + ((k4 * 8) ^ ((n & 7) << 4)));
        *reinterpret_cast<uint2*>(smem + SM_B + off) =
            cvt_f4_bf16x4(__ldg(W4 + i));
    }
    __syncthreads();   // B ready

    const int lr8 = l >> 4;
    const int q   = l & 15;
    const float4* dq = reinterpret_cast<const float4*>(data);
    char* buf = smem + SM_A + w * 4096;
    const int rk = l >> 2;
    const int cx = (l & 3) * 4;
    const uint32_t keysh = (uint32_t)rk << 4;
    char* sB = smem + SM_B;
    float* sD = reinterpret_cast<float*>(smem + SM_D);
    float* red = reinterpret_cast<float*>(smem + SM_RED);
    const unsigned FULL = 0xffffffffu;

    for (int tile = blockIdx.x; tile < 1024; tile += GRID_P) {
        const long g0 = (long)(tile * 128 + w * 32 + lr8) * 256 + q;

        // prefetch chunk 0 RAW (16 clean LDG.128 in flight)
        float4 raw[16];
        #pragma unroll
        for (int i = 0; i < 16; i++)
            raw[i] = __ldg(dq + g0 + (long)i * 512);

        float acc[2][3][4];
        #pragma unroll
        for (int mt = 0; mt < 2; mt++)
            #pragma unroll
            for (int nt = 0; nt < 3; nt++)
                #pragma unroll
                for (int x = 0; x < 4; x++) acc[mt][nt][x] = 0.0f;

        #pragma unroll 1
        for (int c = 0; c < 16; c++) {
            // CVT + STS of current chunk
            #pragma unroll
            for (int i = 0; i < 16; i++) {
                uint2 pk = cvt_f4_bf16x4(raw[i]);
                *reinterpret_cast<uint2*>(
                    buf + (i * 2 + lr8) * 128 +
                    ((q * 8) ^ (((i & 3) * 2 + lr8) << 4))) = pk;
            }
            __syncwarp();

            // prefetch next chunk RAW
            if (c < 15) {
                #pragma unroll
                for (int i = 0; i < 16; i++)
                    raw[i] = __ldg(dq + g0 + (long)i * 512 + (c + 1) * 16);
            }

            // 4 ksteps of k=16
            #pragma unroll
            for (int ks = 0; ks < 4; ks++) {
                const uint32_t a0o = (uint32_t)(rk * 128) +
                    (((uint32_t)(ks * 32 + cx)) ^ keysh);
                uint32_t aA[2][4];
                #pragma unroll
                for (int mt = 0; mt < 2; mt++) {
                    char* bm = buf + mt * 2048;
                    aA[mt][0] = *reinterpret_cast<uint32_t*>(bm + a0o);
                    aA[mt][1] = *reinterpret_cast<uint32_t*>(bm + a0o + 1024);
                    aA[mt][2] = *reinterpret_cast<uint32_t*>(bm + (a0o ^ 16));
                    aA[mt][3] = *reinterpret_cast<uint32_t*>(bm + (a0o ^ 16) + 1024);
                }
                #pragma unroll
                for (int nt = 0; nt < 3; nt++) {
                    const uint32_t b0o = (uint32_t)((nt * 8 + rk) * 2048) +
                        (((uint32_t)(c * 128 + ks * 32 + cx)) ^ keysh);
                    uint32_t bb[2];
                    bb[0] = *reinterpret_cast<uint32_t*>(sB + b0o);
                    bb[1] = *reinterpret_cast<uint32_t*>(sB + (b0o ^ 16));
                    mma16816(acc[0][nt], aA[0], bb);
                    mma16816(acc[1][nt], aA[1], bb);
                }
            }
            __syncwarp();
        }

        // ---- D -> smem (stride 26 floats), per-thread row epilogue ----
        __syncthreads();   // all warps done with A region
        #pragma unroll
        for (int mt = 0; mt < 2; mt++)
            #pragma unroll
            for (int nt = 0; nt < 3; nt++) {
                int r  = w * 32 + mt * 16 + rk;
                int cb = nt * 8 + (l & 3) * 2;
                *reinterpret_cast<float2*>(sD + r * 26 + cb) =
                    make_float2(acc[mt][nt][0], acc[mt][nt][1]);
                *reinterpret_cast<float2*>(sD + (r + 8) * 26 + cb) =
                    make_float2(acc[mt][nt][2], acc[mt][nt][3]);
            }
        __syncthreads();

        const int row = tile * 128 + tid;
        const int s   = row & (SS - 1);

        float emv[TT];
        float m = -1e30f;
        #pragma unroll
        for (int t = 0; t < TT; t++) {
            emv[t] = sD[tid * 26 + t] + __ldg(bias + t);
            m = fmaxf(m, emv[t]);
        }
        float e[TT];
        #pragma unroll
        for (int t = 0; t < TT; t++) e[t] = __expf(emv[t] - m);

        float4* o4 = reinterpret_cast<float4*>(g_eem + (size_t)row * EST);
        o4[0] = make_float4(e[0],  e[1],  e[2],  e[3]);
        o4[1] = make_float4(e[4],  e[5],  e[6],  e[7]);
        o4[2] = make_float4(e[8],  e[9],  e[10], e[11]);
        o4[3] = make_float4(e[12], e[13], e[14], e[15]);
        o4[4] = make_float4(e[16], 0.0f,  0.0f,  0.0f);

        int lab = __ldg(labels + row);
        float em_lab = 0.0f;
        #pragma unroll
        for (int t = 0; t < TT; t++) em_lab = (lab == t) ? emv[t] : em_lab;

        float mk = (__ldg(mask + row) != 0) ? 1.0f : 0.0f;
        float contrib;
        if (s == 0) {
            contrib = __ldg(start + lab) + em_lab;
        } else {
            int prev = __ldg(labels + row - 1);
            contrib = mk * (__ldg(trans + prev * TT + lab) + em_lab);
        }
        float msum_t = mk * m;
        int   mcnt_t = (mk > 0.0f) ? 1 : 0;

        #pragma unroll
        for (int off = 16; off; off >>= 1) {
            contrib += __shfl_xor_sync(FULL, contrib, off);
            msum_t  += __shfl_xor_sync(FULL, msum_t, off);
            mcnt_t  += __shfl_xor_sync(FULL, mcnt_t, off);
        }
        if (l == 0) {
            red[w]     = contrib;
            red[4 + w] = msum_t;
            reinterpret_cast<int*>(red)[8 + w] = mcnt_t;
        }
        __syncthreads();
        if (tid == 0) {
            float sc = 0.0f, sm = 0.0f; int cn = 0;
            #pragma unroll
            for (int ww = 0; ww < 4; ww++) {
                sc += red[ww];
                sm += red[4 + ww];
                cn += reinterpret_cast<int*>(red)[8 + ww];
            }
            g_part_score[tile] = sc;
            g_part_msum[tile]  = sm;
            g_part_mcnt[tile]  = cn;
        }
        __syncthreads();   // red + sD reads done before next tile's STS
    }
}

// ============================================================
// Kernel 2: CRF forward recurrence (linear domain)
//   R14 measured-best: lean 17-shfl branchy step, renorm once
//   per 8-step chunk. 128 blocks x 64 threads, 1 warp per batch.
// ============================================================
__global__ void __launch_bounds__(64)
crf_kernel(const float* __restrict__ trans, const float* __restrict__ start,
           const float* __restrict__ endt, const int* __restrict__ mask)
{
    const unsigned FULL = 0xffffffffu;
    int b = blockIdx.x * 2 + (threadIdx.x >> 5);
    int j = threadIdx.x & 31;
    bool act = (j < TT);

    float Ecol[TT];
    #pragma unroll
    for (int i = 0; i < TT; i++)
        Ecol[i] = act ? __expf(__ldg(trans + i * TT + j)) : 0.0f;
    float eend = act ? __expf(__ldg(endt + j)) : 0.0f;

    const float* eb = g_eem + (size_t)b * (SS * EST);
    const int4* mb = reinterpret_cast<const int4*>(mask + b * SS);

    float bufA[8], bufB[8];
    int   mA[8],  mB[8];

    #pragma unroll
    for (int d = 0; d < 8; d++)
        bufA[d] = act ? __ldg(eb + d * EST + j) : 0.0f;
    {
        int4 a = __ldg(mb + 0), c = __ldg(mb + 1);
        mA[0]=a.x; mA[1]=a.y; mA[2]=a.z; mA[3]=a.w;
        mA[4]=c.x; mA[5]=c.y; mA[6]=c.z; mA[7]=c.w;
    }

    float p = act ? bufA[0] * __expf(__ldg(start + j)) : 0.0f;
    float C = 0.0f;

    // lean step: no per-step renorm (range bounded within a chunk)
    auto step = [&](float eemv, int mkv) {
        if (mkv != 0) {  // warp-uniform
            float a[4] = {0.f, 0.f, 0.f, 0.f};
            #pragma unroll
            for (int i = 0; i < TT; i++)
                a[i & 3] = fmaf(__shfl_sync(FULL, p, i), Ecol[i], a[i & 3]);
            p = ((a[0] + a[1]) + (a[2] + a[3])) * eemv;
        }
    };

    // once-per-chunk renorm: p /= p0, C += log p0 (invariant-preserving)
    auto renorm = [&]() {
        float r = __shfl_sync(FULL, p, 0);
        p *= __fdividef(1.0f, r);
        C += __logf(r);
    };

    #define PREFETCH(cidx, BUF, MARR)                                          \
        do {                                                                    \
            _Pragma("unroll")                                                   \
            for (int d = 0; d < 8; d++)                                         \
                BUF[d] = act ? __ldg(eb + ((cidx) * 8 + d) * EST + j) : 0.0f;   \
            int4 _a = __ldg(mb + 2 * (cidx)), _c = __ldg(mb + 2 * (cidx) + 1);  \
            MARR[0]=_a.x; MARR[1]=_a.y; MARR[2]=_a.z; MARR[3]=_a.w;             \
            MARR[4]=_c.x; MARR[5]=_c.y; MARR[6]=_c.z; MARR[7]=_c.w;             \
        } while (0)

    #define PROCESS(BUF, MARR)                                                  \
        do {                                                                    \
            _Pragma("unroll")                                                   \
            for (int d = 0; d < 8; d++) step(BUF[d], MARR[d]);                  \
            renorm();                                                           \
        } while (0)

    PREFETCH(1, bufB, mB);
    #pragma unroll
    for (int d = 1; d < 8; d++) step(bufA[d], mA[d]);
    renorm();

    for (int cc = 1; cc < 63; cc += 2) {
        PREFETCH(cc + 1, bufA, mA);
        PROCESS(bufB, mB);
        PREFETCH(cc + 2, bufB, mB);
        PROCESS(bufA, mA);
    }
    PROCESS(bufB, mB);

    float term = p * eend;
    #pragma unroll
    for (int off = 16; off; off >>= 1)
        term += __shfl_xor_sync(FULL, term, off);
    if (j == 0) g_denom[b] = C + __logf(term);

    #undef PREFETCH
    #undef PROCESS
}

// ============================================================
// Kernel 3: finalize  out = -mean(score - denom)
// ============================================================
__global__ void __launch_bounds__(256)
fin_kernel(const int* __restrict__ labels, const float* __restrict__ endt,
           float* __restrict__ out)
{
    __shared__ float sred[256];
    int b = threadIdx.x;
    int cnt = 0;
    float psc = 0.0f, pms = 0.0f;
    #pragma unroll
    for (int k = 0; k < 4; k++) {
        cnt += g_part_mcnt[4 * b + k];
        psc += g_part_score[4 * b + k];
        pms += g_part_msum[4 * b + k];
    }
    int lt = __ldg(labels + b * SS + (cnt - 1));
    float score = psc + __ldg(endt + lt);
    float denom = g_denom[b] + pms;
    sred[b] = score - denom;
    __syncthreads();
    #pragma unroll
    for (int off = 128; off; off >>= 1) {
        if (b < off) sred[b] += sred[b + off];
        __syncthreads();
    }
    if (b == 0) out[0] = -sred[0] * (1.0f / BB);
}

// ============================================================
extern "C" void kernel_launch(void* const* d_in, const int* in_sizes, int n_in,
                              void* d_out, int out_size)
{
    const float* data   = (const float*)d_in[0];
    const int*   labels = (const int*)d_in[1];
    const int*   mask   = (const int*)d_in[2];
    const float* W      = (const float*)d_in[3];
    const float* bias   = (const float*)d_in[4];
    const float* start  = (const float*)d_in[5];
    const float* endt   = (const float*)d_in[6];
    const float* trans  = (const float*)d_in[7];

    cudaFuncSetAttribute(emis_kernel,
                         cudaFuncAttributeMaxDynamicSharedMemorySize, SM_TOT);

    emis_kernel<<<GRID_P, 128, SM_TOT>>>(data, labels, mask, W, bias, start, trans);
    crf_kernel<<<BB / 2, 64>>>(trans, start, endt, mask);
    fin_kernel<<<1, 256>>>(labels, endt, (float*)d_out);
}